// round 5
// baseline (speedup 1.0000x reference)
#include <cuda_runtime.h>

#define NN 100000
#define EE 1600000
#define DD 64
#define GG 256

// ---- scratch (no allocs allowed) ----
__device__ float g_agg[NN * DD];
__device__ float g_hA[NN * DD];
__device__ float g_hB[NN * DD];
__device__ int   g_is32;

// ---------------------------------------------------------------------------
// dtype detector: edge_index declared int64 in the reference, but JAX may have
// silently downcast to int32 (x64 disabled). If data is int64, every high
// 32-bit word of the first 256 qwords is 0. If int32, the high words are the
// odd-indexed random indices (virtually never all zero).
// ---------------------------------------------------------------------------
__global__ void detect_kernel(const unsigned long long* __restrict__ ei) {
    __shared__ int s;
    if (threadIdx.x == 0) s = 0;
    __syncthreads();
    unsigned long long v = ei[threadIdx.x];
    if (v >> 32) s = 1;
    __syncthreads();
    if (threadIdx.x == 0) g_is32 = s;
}

// ---------------------------------------------------------------------------
// agg = src  (vectorized copy, layer-0 self term)
// ---------------------------------------------------------------------------
__global__ void copy_kernel(const float4* __restrict__ src, float4* __restrict__ dst) {
    int i = blockIdx.x * blockDim.x + threadIdx.x;
    if (i < NN * DD / 4) dst[i] = src[i];
}

__device__ __forceinline__ void atomic_add_f4(float4* addr, float4 v) {
#if __CUDA_ARCH__ >= 900
    atomicAdd(addr, v);
#else
    float* f = (float*)addr;
    atomicAdd(f + 0, v.x); atomicAdd(f + 1, v.y);
    atomicAdd(f + 2, v.z); atomicAdd(f + 3, v.w);
#endif
}

// ---------------------------------------------------------------------------
// scatter: agg[dst] += h[src] over all edges. 8 threads per edge, 2 float4
// each (full 64-float row). Rows are L2-resident (25.6 MB), so this is an
// LTS-bandwidth/atomic-throughput kernel.
// ---------------------------------------------------------------------------
__global__ __launch_bounds__(256) void scatter_kernel(
    const float4* __restrict__ h, const void* __restrict__ ei,
    float4* __restrict__ agg)
{
    int t = blockIdx.x * 256 + threadIdx.x;
    if (t >= EE * 8) return;
    int e = t >> 3;
    int c = t & 7;
    int src, dst;
    if (g_is32) {
        const int* p = (const int*)ei;
        src = __ldg(&p[e]);
        dst = __ldg(&p[EE + e]);
    } else {
        const long long* p = (const long long*)ei;
        src = (int)__ldg(&p[e]);
        dst = (int)__ldg(&p[EE + e]);
    }
    float4 v0 = h[src * 16 + c];
    float4 v1 = h[src * 16 + c + 8];
    atomic_add_f4(&agg[dst * 16 + c], v0);
    atomic_add_f4(&agg[dst * 16 + c + 8], v1);
}

// ---------------------------------------------------------------------------
// 64x64 register-tiled GEMM helper: acc[4][4] += sZ(64x64, stride 68) @ sW(64x64)
// thread (tx,ty): rows r0..r0+3, cols 4tx..4tx+3.
// ---------------------------------------------------------------------------
__device__ __forceinline__ void mm_tile(const float* __restrict__ sW,
                                        const float* __restrict__ sZ,
                                        float acc[4][4], int tx, int r0)
{
#pragma unroll
    for (int i = 0; i < 4; i++)
#pragma unroll
        for (int j = 0; j < 4; j++) acc[i][j] = 0.f;

#pragma unroll 4
    for (int k4 = 0; k4 < 16; k4++) {
        float zr[4][4];
#pragma unroll
        for (int i = 0; i < 4; i++) {
            float4 t = *(const float4*)&sZ[(r0 + i) * 68 + k4 * 4];
            zr[i][0] = t.x; zr[i][1] = t.y; zr[i][2] = t.z; zr[i][3] = t.w;
        }
#pragma unroll
        for (int kk = 0; kk < 4; kk++) {
            float4 w = *(const float4*)&sW[(k4 * 4 + kk) * 64 + tx * 4];
#pragma unroll
            for (int i = 0; i < 4; i++) {
                acc[i][0] += zr[i][kk] * w.x;
                acc[i][1] += zr[i][kk] * w.y;
                acc[i][2] += zr[i][kk] * w.z;
                acc[i][3] += zr[i][kk] * w.w;
            }
        }
    }
}

// ---------------------------------------------------------------------------
// MLP: hout = relu?( relu(z @ W1 + b1) @ W2 + b2 ), optional dual write to
// aggout (seeds next layer's self term, saving a full copy pass).
// One 64-node tile per block, 256 threads, 4x4 microtiles.
// ---------------------------------------------------------------------------
__global__ __launch_bounds__(256, 4) void mlp_kernel(
    const float* __restrict__ z,
    const float* __restrict__ w1, const float* __restrict__ b1,
    const float* __restrict__ w2, const float* __restrict__ b2,
    float* __restrict__ hout, float* __restrict__ aggout, int relu_out)
{
    __shared__ float sW[64 * 64];
    __shared__ float sZ[64 * 68];
    __shared__ float sB1[64];
    __shared__ float sB2[64];

    int tid = threadIdx.x;
    for (int i = tid; i < 4096; i += 256) sW[i] = w1[i];
    if (tid < 64) { sB1[tid] = b1[tid]; sB2[tid] = b2[tid]; }

    int node0 = blockIdx.x * 64;
#pragma unroll
    for (int j = 0; j < 4; j++) {
        int q = tid + j * 256;
        int r = q >> 4, c = q & 15;
        int node = node0 + r;
        float4 v = make_float4(0.f, 0.f, 0.f, 0.f);
        if (node < NN) v = ((const float4*)z)[node * 16 + c];
        *(float4*)&sZ[r * 68 + c * 4] = v;
    }
    __syncthreads();

    int tx = tid & 15, ty = tid >> 4;
    int r0 = ty * 4;
    float acc[4][4];

    mm_tile(sW, sZ, acc, tx, r0);
    __syncthreads();  // all reads of sW (W1) and sZ (z) complete

    // reload W2, write relu(hidden+b1) back into sZ
    for (int i = tid; i < 4096; i += 256) sW[i] = w2[i];
#pragma unroll
    for (int i = 0; i < 4; i++) {
        float4 h;
        h.x = fmaxf(acc[i][0] + sB1[tx * 4 + 0], 0.f);
        h.y = fmaxf(acc[i][1] + sB1[tx * 4 + 1], 0.f);
        h.z = fmaxf(acc[i][2] + sB1[tx * 4 + 2], 0.f);
        h.w = fmaxf(acc[i][3] + sB1[tx * 4 + 3], 0.f);
        *(float4*)&sZ[(r0 + i) * 68 + tx * 4] = h;
    }
    __syncthreads();

    mm_tile(sW, sZ, acc, tx, r0);

#pragma unroll
    for (int i = 0; i < 4; i++) {
        int node = node0 + r0 + i;
        if (node < NN) {
            float4 o;
            o.x = acc[i][0] + sB2[tx * 4 + 0];
            o.y = acc[i][1] + sB2[tx * 4 + 1];
            o.z = acc[i][2] + sB2[tx * 4 + 2];
            o.w = acc[i][3] + sB2[tx * 4 + 3];
            if (relu_out) {
                o.x = fmaxf(o.x, 0.f); o.y = fmaxf(o.y, 0.f);
                o.z = fmaxf(o.z, 0.f); o.w = fmaxf(o.w, 0.f);
            }
            ((float4*)hout)[node * 16 + tx] = o;
            if (aggout) ((float4*)aggout)[node * 16 + tx] = o;
        }
    }
}

// ---------------------------------------------------------------------------
// out[g] = fc_b  (256 graphs)
// ---------------------------------------------------------------------------
__global__ void init_out_kernel(float* __restrict__ out, const float* __restrict__ fcb) {
    if (threadIdx.x < GG) out[threadIdx.x] = fcb[0];
}

// ---------------------------------------------------------------------------
// fused global_add_pool + FC: out[batch[n]] += dot(h[n], fc_w). Warp per node.
// ---------------------------------------------------------------------------
__global__ __launch_bounds__(256) void pool_kernel(
    const float* __restrict__ h, const void* __restrict__ batch,
    const float* __restrict__ fcw, float* __restrict__ out)
{
    int warp = (blockIdx.x * 256 + threadIdx.x) >> 5;
    int lane = threadIdx.x & 31;
    if (warp >= NN) return;
    float v = h[warp * 64 + lane] * __ldg(&fcw[lane])
            + h[warp * 64 + 32 + lane] * __ldg(&fcw[32 + lane]);
#pragma unroll
    for (int o = 16; o; o >>= 1) v += __shfl_xor_sync(0xffffffffu, v, o);
    if (lane == 0) {
        int g;
        if (g_is32) g = ((const int*)batch)[warp];
        else        g = (int)((const long long*)batch)[warp];
        atomicAdd(&out[g], v);
    }
}

// ---------------------------------------------------------------------------
extern "C" void kernel_launch(void* const* d_in, const int* in_sizes, int n_in,
                              void* d_out, int out_size)
{
    const float* x    = (const float*)d_in[0];
    const void*  ei   = d_in[1];
    const void*  bat  = d_in[2];
    const float* w1[3], *b1[3], *w2[3], *b2[3];
    for (int l = 0; l < 3; l++) {
        w1[l] = (const float*)d_in[3 + 4 * l];
        b1[l] = (const float*)d_in[4 + 4 * l];
        w2[l] = (const float*)d_in[5 + 4 * l];
        b2[l] = (const float*)d_in[6 + 4 * l];
    }
    const float* fcw = (const float*)d_in[15];
    const float* fcb = (const float*)d_in[16];
    float* out = (float*)d_out;

    float *agg, *hA, *hB;
    cudaGetSymbolAddress((void**)&agg, g_agg);
    cudaGetSymbolAddress((void**)&hA,  g_hA);
    cudaGetSymbolAddress((void**)&hB,  g_hB);

    const int scatter_blocks = (EE * 8 + 255) / 256;   // 50000
    const int copy_blocks    = (NN * DD / 4 + 255) / 256;
    const int mlp_blocks     = (NN + 63) / 64;          // 1563
    const int pool_blocks    = (NN * 32 + 255) / 256;   // 12500

    detect_kernel<<<1, 256>>>((const unsigned long long*)ei);

    // layer 0
    copy_kernel<<<copy_blocks, 256>>>((const float4*)x, (float4*)agg);
    scatter_kernel<<<scatter_blocks, 256>>>((const float4*)x, ei, (float4*)agg);
    mlp_kernel<<<mlp_blocks, 256>>>(agg, w1[0], b1[0], w2[0], b2[0], hA, agg, 1);

    // layer 1 (agg already seeded with h0 by previous mlp)
    scatter_kernel<<<scatter_blocks, 256>>>((const float4*)hA, ei, (float4*)agg);
    mlp_kernel<<<mlp_blocks, 256>>>(agg, w1[1], b1[1], w2[1], b2[1], hB, agg, 1);

    // layer 2
    scatter_kernel<<<scatter_blocks, 256>>>((const float4*)hB, ei, (float4*)agg);
    mlp_kernel<<<mlp_blocks, 256>>>(agg, w1[2], b1[2], w2[2], b2[2], hA, (float*)0, 0);

    // pool + fc
    init_out_kernel<<<1, 256>>>(out, fcb);
    pool_kernel<<<pool_blocks, 256>>>(hA, bat, fcw, out);
}

// round 6
// speedup vs baseline: 1.2688x; 1.2688x over previous
#include <cuda_runtime.h>

#define NN 100000
#define EE 1600000
#define DD 64
#define GG 256
#define NPART 98   // ceil(NN/1024)

// ---- scratch (no allocs allowed) ----
__device__ float g_agg[NN * DD];
__device__ float g_hA[NN * DD];
__device__ float g_hB[NN * DD];
__device__ int   g_is32;
__device__ int   g_deg[NN];
__device__ int   g_off[NN + 1];
__device__ int   g_part[128];
__device__ int   g_cursor[NN];
__device__ int   g_csr[EE];
__device__ int   g_src32[EE];
__device__ int   g_dst32[EE];

// ---------------------------------------------------------------------------
// dtype detector: if edge_index really is int64, the high 32-bit word of every
// qword among the first 256 is 0 (indices < 100000). If int32, high words are
// random indices — virtually never all zero.
// ---------------------------------------------------------------------------
__global__ void detect_kernel(const unsigned long long* __restrict__ ei) {
    __shared__ int s;
    if (threadIdx.x == 0) s = 0;
    __syncthreads();
    if (ei[threadIdx.x] >> 32) s = 1;
    __syncthreads();
    if (threadIdx.x == 0) g_is32 = s;
}

__global__ void zero_deg_kernel() {
    int i = blockIdx.x * blockDim.x + threadIdx.x;
    if (i < NN) g_deg[i] = 0;
}

// convert indices to int32 arrays + destination histogram, one pass
__global__ __launch_bounds__(256) void convert_hist_kernel(const void* __restrict__ ei) {
    int e = blockIdx.x * 256 + threadIdx.x;
    if (e >= EE) return;
    int s, d;
    if (g_is32) {
        const int* p = (const int*)ei;
        s = __ldg(&p[e]); d = __ldg(&p[EE + e]);
    } else {
        const long long* p = (const long long*)ei;
        s = (int)__ldg(&p[e]); d = (int)__ldg(&p[EE + e]);
    }
    g_src32[e] = s;
    g_dst32[e] = d;
    atomicAdd(&g_deg[d], 1);
}

// ---- 2-level exclusive scan of g_deg -> g_off ----
__global__ __launch_bounds__(1024) void scan1_kernel() {
    __shared__ int s[1024];
    int tid = threadIdx.x;
    int i = blockIdx.x * 1024 + tid;
    int v = (i < NN) ? g_deg[i] : 0;
    s[tid] = v;
    __syncthreads();
#pragma unroll
    for (int d = 1; d < 1024; d <<= 1) {
        int t = (tid >= d) ? s[tid - d] : 0;
        __syncthreads();
        s[tid] += t;
        __syncthreads();
    }
    if (i < NN) g_off[i] = s[tid] - v;          // exclusive within block
    if (tid == 1023) g_part[blockIdx.x] = s[1023];
}

__global__ void scan2_kernel() {
    __shared__ int s[128];
    int tid = threadIdx.x;
    int v = (tid < NPART) ? g_part[tid] : 0;
    s[tid] = v;
    __syncthreads();
#pragma unroll
    for (int d = 1; d < 128; d <<= 1) {
        int t = (tid >= d) ? s[tid - d] : 0;
        __syncthreads();
        s[tid] += t;
        __syncthreads();
    }
    if (tid < NPART) g_part[tid] = s[tid] - v;  // exclusive
}

__global__ void scan3_kernel() {
    int i = blockIdx.x * blockDim.x + threadIdx.x;
    if (i < NN) {
        int o = g_off[i] + g_part[i >> 10];
        g_off[i] = o;
        g_cursor[i] = o;
    }
    if (i == 0) g_off[NN] = EE;
}

__global__ __launch_bounds__(256) void fill_kernel() {
    int e = blockIdx.x * 256 + threadIdx.x;
    if (e >= EE) return;
    int d = g_dst32[e];
    int pos = atomicAdd(&g_cursor[d], 1);
    g_csr[pos] = g_src32[e];
}

// ---------------------------------------------------------------------------
// gather: z[d] = h[d] + sum_{s in csr[d]} h[s].  16 threads per node (one
// float4 column each); coalesced 256B row reads, plain stores (no atomics).
// ---------------------------------------------------------------------------
__global__ __launch_bounds__(256) void gather_kernel(
    const float4* __restrict__ h, float4* __restrict__ z)
{
    int t = blockIdx.x * 256 + threadIdx.x;
    if (t >= NN * 16) return;
    int node = t >> 4, c = t & 15;
    float4 acc = h[node * 16 + c];              // self term (eps = 0)
    int i = g_off[node], end = g_off[node + 1];
    int s_next = (i < end) ? __ldg(&g_csr[i]) : 0;
    while (i < end) {
        int s = s_next;
        i++;
        if (i < end) s_next = __ldg(&g_csr[i]);  // prefetch next index
        float4 v = h[s * 16 + c];
        acc.x += v.x; acc.y += v.y; acc.z += v.z; acc.w += v.w;
    }
    z[node * 16 + c] = acc;
}

// ---------------------------------------------------------------------------
// GEMM microkernel: acc[8][4] = sZ(128x64, stride 68) @ sW(64x64)
// thread (tx,ty): rows r0..r0+7, cols 4tx..4tx+3.
// 12 LDS.128 per 128 FFMA -> FMA-bound (crossbar 48cyc < FFMA 64cyc / warp-iter)
// ---------------------------------------------------------------------------
__device__ __forceinline__ void mm_tile8(const float* __restrict__ sW,
                                         const float* __restrict__ sZ,
                                         float acc[8][4], int tx, int r0)
{
#pragma unroll
    for (int i = 0; i < 8; i++)
#pragma unroll
        for (int j = 0; j < 4; j++) acc[i][j] = 0.f;

#pragma unroll 2
    for (int k4 = 0; k4 < 16; k4++) {
        float4 w[4];
#pragma unroll
        for (int kk = 0; kk < 4; kk++)
            w[kk] = *(const float4*)&sW[(k4 * 4 + kk) * 64 + tx * 4];
#pragma unroll
        for (int i = 0; i < 8; i++) {
            // broadcast LDS: address independent of tx -> conflict-free
            float4 zv = *(const float4*)&sZ[(r0 + i) * 68 + k4 * 4];
            acc[i][0] += zv.x * w[0].x; acc[i][1] += zv.x * w[0].y;
            acc[i][2] += zv.x * w[0].z; acc[i][3] += zv.x * w[0].w;
            acc[i][0] += zv.y * w[1].x; acc[i][1] += zv.y * w[1].y;
            acc[i][2] += zv.y * w[1].z; acc[i][3] += zv.y * w[1].w;
            acc[i][0] += zv.z * w[2].x; acc[i][1] += zv.z * w[2].y;
            acc[i][2] += zv.z * w[2].z; acc[i][3] += zv.z * w[2].w;
            acc[i][0] += zv.w * w[3].x; acc[i][1] += zv.w * w[3].y;
            acc[i][2] += zv.w * w[3].z; acc[i][3] += zv.w * w[3].w;
        }
    }
}

// ---------------------------------------------------------------------------
// MLP: hout = relu?( relu(z @ W1 + b1) @ W2 + b2 ).  128-node tile per block.
// ---------------------------------------------------------------------------
__global__ __launch_bounds__(256, 2) void mlp_kernel(
    const float* __restrict__ z,
    const float* __restrict__ w1, const float* __restrict__ b1,
    const float* __restrict__ w2, const float* __restrict__ b2,
    float* __restrict__ hout, int relu_out)
{
    __shared__ float sW[64 * 64];
    __shared__ float sZ[128 * 68];
    __shared__ float sB1[64];
    __shared__ float sB2[64];

    int tid = threadIdx.x;
    for (int i = tid; i < 4096; i += 256) sW[i] = w1[i];
    if (tid < 64) { sB1[tid] = b1[tid]; sB2[tid] = b2[tid]; }

    int node0 = blockIdx.x * 128;
#pragma unroll
    for (int j = 0; j < 8; j++) {
        int q = tid + j * 256;
        int r = q >> 4, c = q & 15;
        int node = node0 + r;
        float4 v = make_float4(0.f, 0.f, 0.f, 0.f);
        if (node < NN) v = ((const float4*)z)[node * 16 + c];
        *(float4*)&sZ[r * 68 + c * 4] = v;
    }
    __syncthreads();

    int tx = tid & 15, ty = tid >> 4;
    int r0 = ty * 8;
    float acc[8][4];

    mm_tile8(sW, sZ, acc, tx, r0);
    __syncthreads();  // all reads of W1 / z complete

    for (int i = tid; i < 4096; i += 256) sW[i] = w2[i];
#pragma unroll
    for (int i = 0; i < 8; i++) {
        float4 h;
        h.x = fmaxf(acc[i][0] + sB1[tx * 4 + 0], 0.f);
        h.y = fmaxf(acc[i][1] + sB1[tx * 4 + 1], 0.f);
        h.z = fmaxf(acc[i][2] + sB1[tx * 4 + 2], 0.f);
        h.w = fmaxf(acc[i][3] + sB1[tx * 4 + 3], 0.f);
        *(float4*)&sZ[(r0 + i) * 68 + tx * 4] = h;
    }
    __syncthreads();

    mm_tile8(sW, sZ, acc, tx, r0);

#pragma unroll
    for (int i = 0; i < 8; i++) {
        int node = node0 + r0 + i;
        if (node < NN) {
            float4 o;
            o.x = acc[i][0] + sB2[tx * 4 + 0];
            o.y = acc[i][1] + sB2[tx * 4 + 1];
            o.z = acc[i][2] + sB2[tx * 4 + 2];
            o.w = acc[i][3] + sB2[tx * 4 + 3];
            if (relu_out) {
                o.x = fmaxf(o.x, 0.f); o.y = fmaxf(o.y, 0.f);
                o.z = fmaxf(o.z, 0.f); o.w = fmaxf(o.w, 0.f);
            }
            ((float4*)hout)[node * 16 + tx] = o;
        }
    }
}

// ---------------------------------------------------------------------------
__global__ void init_out_kernel(float* __restrict__ out, const float* __restrict__ fcb) {
    if (threadIdx.x < GG) out[threadIdx.x] = fcb[0];
}

// fused global_add_pool + FC: out[batch[n]] += dot(h[n], fc_w). Warp per node.
__global__ __launch_bounds__(256) void pool_kernel(
    const float* __restrict__ h, const void* __restrict__ batch,
    const float* __restrict__ fcw, float* __restrict__ out)
{
    int warp = (blockIdx.x * 256 + threadIdx.x) >> 5;
    int lane = threadIdx.x & 31;
    if (warp >= NN) return;
    float v = h[warp * 64 + lane] * __ldg(&fcw[lane])
            + h[warp * 64 + 32 + lane] * __ldg(&fcw[32 + lane]);
#pragma unroll
    for (int o = 16; o; o >>= 1) v += __shfl_xor_sync(0xffffffffu, v, o);
    if (lane == 0) {
        int g;
        if (g_is32) g = ((const int*)batch)[warp];
        else        g = (int)((const long long*)batch)[warp];
        atomicAdd(&out[g], v);
    }
}

// ---------------------------------------------------------------------------
extern "C" void kernel_launch(void* const* d_in, const int* in_sizes, int n_in,
                              void* d_out, int out_size)
{
    const float* x   = (const float*)d_in[0];
    const void*  ei  = d_in[1];
    const void*  bat = d_in[2];
    const float* w1[3], *b1[3], *w2[3], *b2[3];
    for (int l = 0; l < 3; l++) {
        w1[l] = (const float*)d_in[3 + 4 * l];
        b1[l] = (const float*)d_in[4 + 4 * l];
        w2[l] = (const float*)d_in[5 + 4 * l];
        b2[l] = (const float*)d_in[6 + 4 * l];
    }
    const float* fcw = (const float*)d_in[15];
    const float* fcb = (const float*)d_in[16];
    float* out = (float*)d_out;

    float *agg, *hA, *hB;
    cudaGetSymbolAddress((void**)&agg, g_agg);
    cudaGetSymbolAddress((void**)&hA,  g_hA);
    cudaGetSymbolAddress((void**)&hB,  g_hB);

    const int edge_blocks   = (EE + 255) / 256;          // 6250
    const int gather_blocks = (NN * 16 + 255) / 256;     // 6250
    const int mlp_blocks    = (NN + 127) / 128;          // 782
    const int node_blocks   = (NN + 255) / 256;
    const int pool_blocks   = (NN * 32 + 255) / 256;

    // ---- CSR-by-destination build (per call; graph-capturable) ----
    detect_kernel<<<1, 256>>>((const unsigned long long*)ei);
    zero_deg_kernel<<<node_blocks, 256>>>();
    convert_hist_kernel<<<edge_blocks, 256>>>(ei);
    scan1_kernel<<<NPART, 1024>>>();
    scan2_kernel<<<1, 128>>>();
    scan3_kernel<<<node_blocks, 256>>>();
    fill_kernel<<<edge_blocks, 256>>>();

    // ---- layer 0 ----
    gather_kernel<<<gather_blocks, 256>>>((const float4*)x, (float4*)agg);
    mlp_kernel<<<mlp_blocks, 256>>>(agg, w1[0], b1[0], w2[0], b2[0], hA, 1);
    // ---- layer 1 ----
    gather_kernel<<<gather_blocks, 256>>>((const float4*)hA, (float4*)agg);
    mlp_kernel<<<mlp_blocks, 256>>>(agg, w1[1], b1[1], w2[1], b2[1], hB, 1);
    // ---- layer 2 ----
    gather_kernel<<<gather_blocks, 256>>>((const float4*)hB, (float4*)agg);
    mlp_kernel<<<mlp_blocks, 256>>>(agg, w1[2], b1[2], w2[2], b2[2], hA, 0);

    // ---- pool + fc ----
    init_out_kernel<<<1, 256>>>(out, fcb);
    pool_kernel<<<pool_blocks, 256>>>(hA, bat, fcw, out);
}